// round 10
// baseline (speedup 1.0000x reference)
#include <cuda_runtime.h>
#include <cuda_bf16.h>
#include <math.h>
#include <stdint.h>

#define HID   256
#define NB    4096
#define NN    204800
#define HF4   1024
#define INV_SCALE 0.17677669529663687f

// ---------------- fp32 scratch ----------------
__device__ float g_u [NB * HID];
__device__ float g_rvec[HID];
__device__ float g_wcvec[HID];
__device__ float g_c0;
__device__ float g_c [NB];
__device__ float g_escore[NN];
__device__ float g_dh[NB * HID];
__device__ float g_x1[NB * HID];
__device__ float g_hp[4 * NB * HID];
__device__ int   g_segstart[NB + 1];

// ---------------- bf16 hi/lo scratch (16B-vector accessed) ----------------
__device__ __align__(256) __nv_bfloat16 g_wqh[HID * HID],  g_wql[HID * HID];
__device__ __align__(256) __nv_bfloat16 g_wkTh[HID * HID], g_wkTl[HID * HID];
__device__ __align__(256) __nv_bfloat16 g_mh[HID * HID],   g_ml[HID * HID];
__device__ __align__(256) __nv_bfloat16 g_smh[NB * HID],   g_sml[NB * HID];
__device__ __align__(256) __nv_bfloat16 g_shi[NB * HID],   g_slo[NB * HID];
__device__ __align__(256) __nv_bfloat16 g_x1h[NB * HID],   g_x1l[NB * HID];
__device__ __align__(256) __nv_bfloat16 g_h1h[NB * HF4],   g_h1l[NB * HF4];
__device__ __align__(256) __nv_bfloat16 g_wvh[HID * HID],  g_wvl[HID * HID];
__device__ __align__(256) __nv_bfloat16 g_w1h[HID * HF4],  g_w1l[HID * HF4];
__device__ __align__(256) __nv_bfloat16 g_w2h[HF4 * HID],  g_w2l[HF4 * HID];

// ---------------- helpers ----------------
__device__ __forceinline__ float warp_sum(float v) {
#pragma unroll
    for (int o = 16; o; o >>= 1) v += __shfl_xor_sync(0xffffffffu, v, o);
    return v;
}

__device__ __forceinline__ float block_sum_256(float v) {
    __shared__ float sh[8];
    int lane = threadIdx.x & 31, w = threadIdx.x >> 5;
    v = warp_sum(v);
    if (lane == 0) sh[w] = v;
    __syncthreads();
    float r = (lane < 8) ? sh[lane] : 0.f;
    r = warp_sum(r);
    __syncthreads();
    return r;
}

__device__ __forceinline__ uint32_t s2u(const void* p) {
    return (uint32_t)__cvta_generic_to_shared(p);
}
__device__ __forceinline__ void ldsm4(uint32_t& r0, uint32_t& r1, uint32_t& r2, uint32_t& r3, uint32_t addr) {
    asm volatile("ldmatrix.sync.aligned.m8n8.x4.shared.b16 {%0,%1,%2,%3}, [%4];"
                 : "=r"(r0), "=r"(r1), "=r"(r2), "=r"(r3) : "r"(addr));
}
__device__ __forceinline__ void ldsm4t(uint32_t& r0, uint32_t& r1, uint32_t& r2, uint32_t& r3, uint32_t addr) {
    asm volatile("ldmatrix.sync.aligned.m8n8.x4.trans.shared.b16 {%0,%1,%2,%3}, [%4];"
                 : "=r"(r0), "=r"(r1), "=r"(r2), "=r"(r3) : "r"(addr));
}
__device__ __forceinline__ void mma16816(float* c, const uint32_t* a, const uint32_t* b) {
    asm volatile("mma.sync.aligned.m16n8k16.row.col.f32.bf16.bf16.f32 "
                 "{%0,%1,%2,%3},{%4,%5,%6,%7},{%8,%9},{%0,%1,%2,%3};"
                 : "+f"(c[0]), "+f"(c[1]), "+f"(c[2]), "+f"(c[3])
                 : "r"(a[0]), "r"(a[1]), "r"(a[2]), "r"(a[3]), "r"(b[0]), "r"(b[1]));
}
__device__ __forceinline__ void split1(float v, __nv_bfloat16& h, __nv_bfloat16& l) {
    h = __float2bfloat16(v);
    l = __float2bfloat16(v - __bfloat162float(h));
}
__device__ __forceinline__ void split4(float4 v, uint2& h, uint2& l) {
    __nv_bfloat16 h0, h1, h2, h3, l0, l1, l2, l3;
    split1(v.x, h0, l0); split1(v.y, h1, l1); split1(v.z, h2, l2); split1(v.w, h3, l3);
    union { __nv_bfloat162 b2[2]; uint2 u; } th, tl;
    th.b2[0] = __halves2bfloat162(h0, h1); th.b2[1] = __halves2bfloat162(h2, h3);
    tl.b2[0] = __halves2bfloat162(l0, l1); tl.b2[1] = __halves2bfloat162(l2, l3);
    h = th.u; l = tl.u;
}

// ---------------- small kernels ----------------
__global__ void seg_kernel(const int* __restrict__ batch) {
    int b = blockIdx.x * blockDim.x + threadIdx.x;
    if (b > NB) return;
    int lo = 0, hi = NN;
    while (lo < hi) { int mid = (lo + hi) >> 1; if (batch[mid] < b) lo = mid + 1; else hi = mid; }
    g_segstart[b] = lo;
}

// wk -> wkT as hi/lo bf16
__global__ void transpose_k(const float* __restrict__ in) {
    __shared__ float tile[32][33];
    int bx = blockIdx.x * 32, by = blockIdx.y * 32;
#pragma unroll
    for (int i = 0; i < 32; i += 8)
        tile[threadIdx.y + i][threadIdx.x] = in[(size_t)(by + threadIdx.y + i) * HID + bx + threadIdx.x];
    __syncthreads();
#pragma unroll
    for (int i = 0; i < 32; i += 8) {
        float v = tile[threadIdx.x][threadIdx.y + i];
        size_t o = (size_t)(bx + threadIdx.y + i) * HID + by + threadIdx.x;
        __nv_bfloat16 h, l; split1(v, h, l);
        g_wkTh[o] = h; g_wkTl[o] = l;
    }
}

// wcvec = wq @ bk ; rvec = bq @ wk^T ; c0 = bq.bk ; also emits wq hi/lo
__global__ void prep_kernel(const float* __restrict__ wq, const float* __restrict__ wk,
                            const float* __restrict__ bq, const float* __restrict__ bk) {
    int gw = (blockIdx.x * blockDim.x + threadIdx.x) >> 5;
    int lane = threadIdx.x & 31;
    if (gw > 2 * HID) return;
    const float* rowp;
    const float* vecp;
    if (gw < HID)            { rowp = wq + (size_t)gw * HID;          vecp = bk; }
    else if (gw < 2 * HID)   { rowp = wk + (size_t)(gw - HID) * HID;  vecp = bq; }
    else                     { rowp = bq;                             vecp = bk; }
    float acc = 0.f;
#pragma unroll
    for (int t = 0; t < HID / 32; t++) {
        float v = rowp[lane + 32 * t];
        acc += v * vecp[lane + 32 * t];
        if (gw < HID) {
            __nv_bfloat16 h, l; split1(v, h, l);
            size_t o = (size_t)gw * HID + lane + 32 * t;
            g_wqh[o] = h; g_wql[o] = l;
        }
    }
    acc = warp_sum(acc);
    if (lane == 0) {
        if (gw < HID)          g_wcvec[gw] = acc;
        else if (gw < 2 * HID) g_rvec[gw - HID] = acc;
        else                   g_c0 = acc;
    }
}

// c[b] = smiles[b].wcvec + c0 ; also emits smiles hi/lo
__global__ void c_kernel(const float* __restrict__ smiles) {
    int gw = (blockIdx.x * blockDim.x + threadIdx.x) >> 5;
    int lane = threadIdx.x & 31;
    if (gw >= NB) return;
    const float* sp = smiles + (size_t)gw * HID;
    float acc = 0.f;
#pragma unroll
    for (int t = 0; t < HID / 32; t++) {
        float v = sp[lane + 32 * t];
        acc += v * g_wcvec[lane + 32 * t];
        __nv_bfloat16 h, l; split1(v, h, l);
        size_t o = (size_t)gw * HID + lane + 32 * t;
        g_smh[o] = h; g_sml[o] = l;
    }
    acc = warp_sum(acc);
    if (lane == 0) g_c[gw] = acc + g_c0;
}

// one-shot hi/lo convert for wv, w1, w2 (float4 per thread)
__global__ void cvtw_kernel(const float* __restrict__ wv, const float* __restrict__ w1,
                            const float* __restrict__ w2) {
    int i = blockIdx.x * blockDim.x + threadIdx.x;
    const float* src; __nv_bfloat16 *dh, *dl; int off;
    if (i < 16384)       { src = wv; dh = g_wvh; dl = g_wvl; off = i; }
    else if (i < 81920)  { src = w1; dh = g_w1h; dl = g_w1l; off = i - 16384; }
    else if (i < 147456) { src = w2; dh = g_w2h; dl = g_w2l; off = i - 81920; }
    else return;
    float4 v = ((const float4*)src)[off];
    uint2 h, l; split4(v, h, l);
    ((uint2*)dh)[off] = h;
    ((uint2*)dl)[off] = l;
}

// ---------------- split-bf16 GEMM, pre-split operands, round-5 loop skeleton ----------------
// C[M,N] = A[M,K] @ B[K,N] (+bias)(+relu); SPLITK partials; OUTBF16 dual emission.
// BM=128 BN=64 BK=32, 256 threads (8 warps 4x2), warp tile 32x32
#define ASTR 40   // bf16 units per A smem row (32 + 8 pad)
#define BSTR 72   // bf16 units per B smem row (64 + 8 pad)

template<bool BIAS, bool RELU, bool SPLITK, bool OUTBF16>
__global__ __launch_bounds__(256)
void bgemm_kernel(const __nv_bfloat16* __restrict__ Agh, const __nv_bfloat16* __restrict__ Agl,
                  const __nv_bfloat16* __restrict__ Bgh, const __nv_bfloat16* __restrict__ Bgl,
                  const float* __restrict__ bias,
                  float* __restrict__ C, __nv_bfloat16* __restrict__ Ch, __nv_bfloat16* __restrict__ Cl,
                  int M, int N, int K, int lda)
{
    __shared__ __align__(16) __nv_bfloat16 sAh[128 * ASTR], sAl[128 * ASTR];
    __shared__ __align__(16) __nv_bfloat16 sBh[32 * BSTR],  sBl[32 * BSTR];

    const int tid  = threadIdx.x;
    const int lane = tid & 31, wid = tid >> 5;
    const int wm = wid >> 1, wn = wid & 1;
    const int row0 = blockIdx.y * 128, col0 = blockIdx.x * 64;
    const int koff = SPLITK ? blockIdx.z * K : 0;

    float acc[2][4][4];
#pragma unroll
    for (int mi = 0; mi < 2; mi++)
#pragma unroll
        for (int nj = 0; nj < 4; nj++)
#pragma unroll
            for (int q = 0; q < 4; q++) acc[mi][nj][q] = 0.f;

    // A tile: 128x32 bf16 = 512 uint4 chunks, 2/thread; B tile: 32x64 = 256 chunks, 1/thread
    const int ar0 = tid >> 2,         ac0 = (tid & 3) * 8;
    const int ar1 = (tid + 256) >> 2, ac1 = ((tid + 256) & 3) * 8;
    const int br  = tid >> 3,         bc  = (tid & 7) * 8;

    const size_t aoff0 = (size_t)(row0 + ar0) * lda + koff + ac0;
    const size_t aoff1 = (size_t)(row0 + ar1) * lda + koff + ac1;
    const size_t boffg = (size_t)(koff + br) * N + col0 + bc;

    uint4 pAh0, pAh1, pAl0, pAl1, pBh, pBl;
    pAh0 = *(const uint4*)(Agh + aoff0);
    pAh1 = *(const uint4*)(Agh + aoff1);
    pAl0 = *(const uint4*)(Agl + aoff0);
    pAl1 = *(const uint4*)(Agl + aoff1);
    pBh  = *(const uint4*)(Bgh + boffg);
    pBl  = *(const uint4*)(Bgl + boffg);

    const uint32_t sAh_u = s2u(sAh), sAl_u = s2u(sAl), sBh_u = s2u(sBh), sBl_u = s2u(sBl);
    const int a_lrow = wm * 32 + (lane & 15);
    const int a_lcol = ((lane >> 4) & 1) * 8;
    const int b_lrow = (lane & 7) + ((lane >> 3) & 1) * 8;
    const int b_lcol = wn * 32 + ((lane >> 4) & 1) * 8;

    const int NT = K / 32;
    for (int kt = 0; kt < NT; kt++) {
        *(uint4*)&sAh[ar0 * ASTR + ac0] = pAh0;
        *(uint4*)&sAh[ar1 * ASTR + ac1] = pAh1;
        *(uint4*)&sAl[ar0 * ASTR + ac0] = pAl0;
        *(uint4*)&sAl[ar1 * ASTR + ac1] = pAl1;
        *(uint4*)&sBh[br * BSTR + bc]   = pBh;
        *(uint4*)&sBl[br * BSTR + bc]   = pBl;
        __syncthreads();

        if (kt + 1 < NT) {
            size_t ka = (size_t)(kt + 1) * 32;
            pAh0 = *(const uint4*)(Agh + aoff0 + ka);
            pAh1 = *(const uint4*)(Agh + aoff1 + ka);
            pAl0 = *(const uint4*)(Agl + aoff0 + ka);
            pAl1 = *(const uint4*)(Agl + aoff1 + ka);
            pBh  = *(const uint4*)(Bgh + boffg + ka * N);
            pBl  = *(const uint4*)(Bgl + boffg + ka * N);
        }

#pragma unroll
        for (int ks = 0; ks < 2; ks++) {
            uint32_t ah[2][4], al[2][4], bh[4][2], bl[4][2];
#pragma unroll
            for (int mi = 0; mi < 2; mi++) {
                uint32_t aoff = (uint32_t)(((a_lrow + mi * 16) * ASTR + ks * 16 + a_lcol) * 2);
                ldsm4(ah[mi][0], ah[mi][1], ah[mi][2], ah[mi][3], sAh_u + aoff);
                ldsm4(al[mi][0], al[mi][1], al[mi][2], al[mi][3], sAl_u + aoff);
            }
#pragma unroll
            for (int nj2 = 0; nj2 < 2; nj2++) {
                uint32_t boff = (uint32_t)(((ks * 16 + b_lrow) * BSTR + b_lcol + nj2 * 16) * 2);
                uint32_t t0, t1, t2, t3;
                ldsm4t(t0, t1, t2, t3, sBh_u + boff);
                bh[nj2 * 2][0] = t0; bh[nj2 * 2][1] = t1;
                bh[nj2 * 2 + 1][0] = t2; bh[nj2 * 2 + 1][1] = t3;
                ldsm4t(t0, t1, t2, t3, sBl_u + boff);
                bl[nj2 * 2][0] = t0; bl[nj2 * 2][1] = t1;
                bl[nj2 * 2 + 1][0] = t2; bl[nj2 * 2 + 1][1] = t3;
            }
#pragma unroll
            for (int mi = 0; mi < 2; mi++)
#pragma unroll
                for (int nj = 0; nj < 4; nj++) {
                    mma16816(acc[mi][nj], ah[mi], bh[nj]);
                    mma16816(acc[mi][nj], ah[mi], bl[nj]);
                    mma16816(acc[mi][nj], al[mi], bh[nj]);
                }
        }
        __syncthreads();
    }

    float* Cout = SPLITK ? C + (size_t)blockIdx.z * M * N : C;
#pragma unroll
    for (int mi = 0; mi < 2; mi++) {
        int r = row0 + wm * 32 + mi * 16 + (lane >> 2);
#pragma unroll
        for (int nj = 0; nj < 4; nj++) {
            int c = col0 + wn * 32 + nj * 8 + (lane & 3) * 2;
            float b0 = 0.f, b1 = 0.f;
            if (BIAS) { b0 = bias[c]; b1 = bias[c + 1]; }
            float v00 = acc[mi][nj][0] + b0, v01 = acc[mi][nj][1] + b1;
            float v10 = acc[mi][nj][2] + b0, v11 = acc[mi][nj][3] + b1;
            if (RELU) {
                v00 = fmaxf(v00, 0.f); v01 = fmaxf(v01, 0.f);
                v10 = fmaxf(v10, 0.f); v11 = fmaxf(v11, 0.f);
            }
            if (OUTBF16) {
                __nv_bfloat16 h00, l00, h01, l01, h10, l10, h11, l11;
                split1(v00, h00, l00); split1(v01, h01, l01);
                split1(v10, h10, l10); split1(v11, h11, l11);
                *(__nv_bfloat162*)&Ch[(size_t)r * N + c]       = __halves2bfloat162(h00, h01);
                *(__nv_bfloat162*)&Cl[(size_t)r * N + c]       = __halves2bfloat162(l00, l01);
                *(__nv_bfloat162*)&Ch[(size_t)(r + 8) * N + c] = __halves2bfloat162(h10, h11);
                *(__nv_bfloat162*)&Cl[(size_t)(r + 8) * N + c] = __halves2bfloat162(l10, l11);
            } else {
                *(float2*)&Cout[(size_t)r * N + c]       = make_float2(v00, v01);
                *(float2*)&Cout[(size_t)(r + 8) * N + c] = make_float2(v10, v11);
            }
        }
    }
}

// ---------------- attention pieces ----------------
__global__ void score_kernel(const float* __restrict__ key, const int* __restrict__ batch) {
    int gw = (blockIdx.x * blockDim.x + threadIdx.x) >> 5;
    int lane = threadIdx.x & 31;
    if (gw >= NN) return;
    int b = batch[gw];
    const float* kp = key + (size_t)gw * HID;
    const float* up = g_u + (size_t)b  * HID;
    float acc = 0.f;
#pragma unroll
    for (int t = 0; t < HID / 32; t++)
        acc += kp[lane + 32 * t] * up[lane + 32 * t];
    acc = warp_sum(acc);
    if (lane == 0) g_escore[gw] = expf((acc + g_c[b]) * INV_SCALE);
}

// per-graph softmax + weighted value sum; emits S as hi/lo bf16
__global__ void attn_kernel(const float* __restrict__ value, float* __restrict__ att_out) {
    int b = blockIdx.x, t = threadIdx.x;
    int s0 = g_segstart[b], s1 = g_segstart[b + 1];
    float partial = 0.f;
    for (int n = s0 + t; n < s1; n += 256) partial += g_escore[n];
    float denom = block_sum_256(partial);
    float acc = 0.f;
    if (s1 > s0) {
        float invd = 1.f / denom;
        for (int n = s0 + t; n < s1; n += 256) att_out[n] = g_escore[n] * invd;
#pragma unroll 4
        for (int n = s0; n < s1; n++)
            acc += (g_escore[n] * invd) * value[(size_t)n * HID + t];
    }
    __nv_bfloat16 h, l; split1(acc, h, l);
    size_t o = (size_t)b * HID + t;
    g_shi[o] = h; g_slo[o] = l;
}

// out = LN(x + r); also emits hi/lo bf16
__global__ void ln_kernel(const float* __restrict__ x, const float* __restrict__ r,
                          const float* __restrict__ g, const float* __restrict__ b,
                          float* __restrict__ out) {
    int row = blockIdx.x, t = threadIdx.x;
    size_t idx = (size_t)row * HID + t;
    float v = x[idx] + r[idx];
    float mu = block_sum_256(v) * (1.f / HID);
    float d = v - mu;
    float var = block_sum_256(d * d) * (1.f / HID);
    float o = d * rsqrtf(var + 1e-5f) * g[t] + b[t];
    out[idx] = o;
    __nv_bfloat16 h, l; split1(o, h, l);
    g_x1h[idx] = h; g_x1l[idx] = l;
}

// reduce 4 split-K partials + bias, add residual, LN -> out
__global__ void ln2_reduce(const float* __restrict__ x1, const float* __restrict__ c2,
                           const float* __restrict__ g, const float* __restrict__ b,
                           float* __restrict__ out) {
    int row = blockIdx.x, t = threadIdx.x;
    size_t idx = (size_t)row * HID + t;
    const size_t STRIDE = (size_t)NB * HID;
    float h = g_hp[idx] + g_hp[idx + STRIDE] + g_hp[idx + 2 * STRIDE] + g_hp[idx + 3 * STRIDE] + c2[t];
    float v = x1[idx] + h;
    float mu = block_sum_256(v) * (1.f / HID);
    float d = v - mu;
    float var = block_sum_256(d * d) * (1.f / HID);
    out[idx] = d * rsqrtf(var + 1e-5f) * g[t] + b[t];
}

// ---------------- launcher ----------------
extern "C" void kernel_launch(void* const* d_in, const int* in_sizes, int n_in,
                              void* d_out, int out_size) {
    const float* smiles   = (const float*)d_in[0];
    const float* key_in   = (const float*)d_in[1];
    const float* value_in = (const float*)d_in[2];
    const int*   batch    = (const int*)  d_in[3];
    const float* wq   = (const float*)d_in[4];
    const float* bq   = (const float*)d_in[5];
    const float* wk   = (const float*)d_in[6];
    const float* bk   = (const float*)d_in[7];
    const float* wv   = (const float*)d_in[8];
    const float* bv   = (const float*)d_in[9];
    const float* ln0g = (const float*)d_in[10];
    const float* ln0b = (const float*)d_in[11];
    const float* ln1g = (const float*)d_in[12];
    const float* ln1b = (const float*)d_in[13];
    const float* w1   = (const float*)d_in[14];
    const float* c1   = (const float*)d_in[15];
    const float* w2   = (const float*)d_in[16];
    const float* c2   = (const float*)d_in[17];

    float* out        = (float*)d_out;
    float* out_smiles = out;
    float* out_att    = out + (size_t)NB * HID;

    float *U, *Rv, *Dh, *X1, *Hp;
    cudaGetSymbolAddress((void**)&U,  g_u);
    cudaGetSymbolAddress((void**)&Rv, g_rvec);
    cudaGetSymbolAddress((void**)&Dh, g_dh);
    cudaGetSymbolAddress((void**)&X1, g_x1);
    cudaGetSymbolAddress((void**)&Hp, g_hp);

    __nv_bfloat16 *Wqh, *Wql, *WkTh, *WkTl, *Mh, *Ml, *Smh, *Sml, *Shi, *Slo;
    __nv_bfloat16 *X1h, *X1l, *H1h, *H1l, *Wvh, *Wvl, *W1h, *W1l, *W2h, *W2l;
    cudaGetSymbolAddress((void**)&Wqh,  g_wqh);  cudaGetSymbolAddress((void**)&Wql,  g_wql);
    cudaGetSymbolAddress((void**)&WkTh, g_wkTh); cudaGetSymbolAddress((void**)&WkTl, g_wkTl);
    cudaGetSymbolAddress((void**)&Mh,   g_mh);   cudaGetSymbolAddress((void**)&Ml,   g_ml);
    cudaGetSymbolAddress((void**)&Smh,  g_smh);  cudaGetSymbolAddress((void**)&Sml,  g_sml);
    cudaGetSymbolAddress((void**)&Shi,  g_shi);  cudaGetSymbolAddress((void**)&Slo,  g_slo);
    cudaGetSymbolAddress((void**)&X1h,  g_x1h);  cudaGetSymbolAddress((void**)&X1l,  g_x1l);
    cudaGetSymbolAddress((void**)&H1h,  g_h1h);  cudaGetSymbolAddress((void**)&H1l,  g_h1l);
    cudaGetSymbolAddress((void**)&Wvh,  g_wvh);  cudaGetSymbolAddress((void**)&Wvl,  g_wvl);
    cudaGetSymbolAddress((void**)&W1h,  g_w1h);  cudaGetSymbolAddress((void**)&W1l,  g_w1l);
    cudaGetSymbolAddress((void**)&W2h,  g_w2h);  cudaGetSymbolAddress((void**)&W2l,  g_w2l);

    // independent precomputes (+ fused hi/lo emission)
    seg_kernel<<<(NB + 1 + 255) / 256, 256>>>(batch);
    transpose_k<<<dim3(HID / 32, HID / 32), dim3(32, 8)>>>(wk);
    prep_kernel<<<(2 * HID + 1 + 7) / 8, 256>>>(wq, wk, bq, bk);
    c_kernel<<<NB / 8, 256>>>(smiles);
    cvtw_kernel<<<576, 256>>>(wv, w1, w2);

    // M = wq @ wk^T -> bf16 hi/lo
    bgemm_kernel<false, false, false, true><<<dim3(HID / 64, HID / 128), 256>>>(
        Wqh, Wql, WkTh, WkTl, nullptr, nullptr, Mh, Ml, HID, HID, HID, HID);
    // U = smiles @ M + rvec -> fp32
    bgemm_kernel<true, false, false, false><<<dim3(HID / 64, NB / 128), 256>>>(
        Smh, Sml, Mh, Ml, Rv, U, nullptr, nullptr, NB, HID, HID, HID);

    // per-node scores, per-graph softmax + weighted value sum (S -> hi/lo)
    score_kernel<<<NN / 8, 256>>>(key_in, batch);
    attn_kernel<<<NB, 256>>>(value_in, out_att);

    // Dh = S @ wv + bv -> fp32 ; X1 = LN(smiles + Dh) (+ hi/lo)
    bgemm_kernel<true, false, false, false><<<dim3(HID / 64, NB / 128), 256>>>(
        Shi, Slo, Wvh, Wvl, bv, Dh, nullptr, nullptr, NB, HID, HID, HID);
    ln_kernel<<<NB, 256>>>(smiles, Dh, ln0g, ln0b, X1);

    // FFN1: H1 = relu(X1 @ w1 + c1) -> bf16 hi/lo
    bgemm_kernel<true, true, false, true><<<dim3(HF4 / 64, NB / 128), 256>>>(
        X1h, X1l, W1h, W1l, c1, nullptr, H1h, H1l, NB, HF4, HID, HID);
    // FFN2 split-K=4 partials -> fp32
    bgemm_kernel<false, false, true, false><<<dim3(HID / 64, NB / 128, 4), 256>>>(
        H1h, H1l, W2h, W2l, nullptr, Hp, nullptr, nullptr, NB, HID, HF4 / 4, HF4);
    // reduce + c2 + residual + LN -> out
    ln2_reduce<<<NB, 256>>>(X1, c2, ln1g, ln1b, out_smiles);
}

// round 12
// speedup vs baseline: 1.0794x; 1.0794x over previous
#include <cuda_runtime.h>
#include <cuda_bf16.h>
#include <math.h>
#include <stdint.h>

#define HID   256
#define NB    4096
#define NN    204800
#define HF4   1024
#define INV_SCALE 0.17677669529663687f
#define MAXSEG 1024

// ---------------- scratch (static device globals; no allocation) ----------------
__device__ float g_u [NB * HID];
__device__ float g_wkT[HID * HID];
__device__ float g_M  [HID * HID];
__device__ float g_rvec[HID];
__device__ float g_wcvec[HID];
__device__ float g_c0;
__device__ float g_c [NB];
__device__ float g_escore[NN];        // overflow fallback only
__device__ float g_s [NB * HID];
__device__ float g_dh[NB * HID];
__device__ float g_x1[NB * HID];
__device__ float g_h1[NB * HF4];
__device__ float g_hp[4 * NB * HID];  // split-K partials for FFN2
__device__ int   g_segstart[NB + 1];

// ---------------- helpers ----------------
__device__ __forceinline__ float warp_sum(float v) {
#pragma unroll
    for (int o = 16; o; o >>= 1) v += __shfl_xor_sync(0xffffffffu, v, o);
    return v;
}

__device__ __forceinline__ float block_sum_256(float v) {
    __shared__ float sh[8];
    int lane = threadIdx.x & 31, w = threadIdx.x >> 5;
    v = warp_sum(v);
    if (lane == 0) sh[w] = v;
    __syncthreads();
    float r = (lane < 8) ? sh[lane] : 0.f;
    r = warp_sum(r);
    __syncthreads();
    return r;
}

__device__ __forceinline__ uint32_t s2u(const void* p) {
    return (uint32_t)__cvta_generic_to_shared(p);
}

__device__ __forceinline__ void ldsm4(uint32_t& r0, uint32_t& r1, uint32_t& r2, uint32_t& r3, uint32_t addr) {
    asm volatile("ldmatrix.sync.aligned.m8n8.x4.shared.b16 {%0,%1,%2,%3}, [%4];"
                 : "=r"(r0), "=r"(r1), "=r"(r2), "=r"(r3) : "r"(addr));
}
__device__ __forceinline__ void ldsm4t(uint32_t& r0, uint32_t& r1, uint32_t& r2, uint32_t& r3, uint32_t addr) {
    asm volatile("ldmatrix.sync.aligned.m8n8.x4.trans.shared.b16 {%0,%1,%2,%3}, [%4];"
                 : "=r"(r0), "=r"(r1), "=r"(r2), "=r"(r3) : "r"(addr));
}
__device__ __forceinline__ void mma16816(float* c, const uint32_t* a, const uint32_t* b) {
    asm volatile("mma.sync.aligned.m16n8k16.row.col.f32.bf16.bf16.f32 "
                 "{%0,%1,%2,%3},{%4,%5,%6,%7},{%8,%9},{%0,%1,%2,%3};"
                 : "+f"(c[0]), "+f"(c[1]), "+f"(c[2]), "+f"(c[3])
                 : "r"(a[0]), "r"(a[1]), "r"(a[2]), "r"(a[3]), "r"(b[0]), "r"(b[1]));
}

__device__ __forceinline__ void split4(float4 v, uint2& h, uint2& l) {
    __nv_bfloat16 h0 = __float2bfloat16(v.x), h1 = __float2bfloat16(v.y);
    __nv_bfloat16 h2 = __float2bfloat16(v.z), h3 = __float2bfloat16(v.w);
    __nv_bfloat16 l0 = __float2bfloat16(v.x - __bfloat162float(h0));
    __nv_bfloat16 l1 = __float2bfloat16(v.y - __bfloat162float(h1));
    __nv_bfloat16 l2 = __float2bfloat16(v.z - __bfloat162float(h2));
    __nv_bfloat16 l3 = __float2bfloat16(v.w - __bfloat162float(h3));
    union { __nv_bfloat162 b2[2]; uint2 u; } th, tl;
    th.b2[0] = __halves2bfloat162(h0, h1); th.b2[1] = __halves2bfloat162(h2, h3);
    tl.b2[0] = __halves2bfloat162(l0, l1); tl.b2[1] = __halves2bfloat162(l2, l3);
    h = th.u; l = tl.u;
}

// ---------------- small kernels ----------------
__global__ void seg_kernel(const int* __restrict__ batch) {
    int b = blockIdx.x * blockDim.x + threadIdx.x;
    if (b > NB) return;
    int lo = 0, hi = NN;
    while (lo < hi) { int mid = (lo + hi) >> 1; if (batch[mid] < b) lo = mid + 1; else hi = mid; }
    g_segstart[b] = lo;
}

__global__ void transpose_k(const float* __restrict__ in, float* __restrict__ out) {
    __shared__ float tile[32][33];
    int bx = blockIdx.x * 32, by = blockIdx.y * 32;
#pragma unroll
    for (int i = 0; i < 32; i += 8)
        tile[threadIdx.y + i][threadIdx.x] = in[(size_t)(by + threadIdx.y + i) * HID + bx + threadIdx.x];
    __syncthreads();
#pragma unroll
    for (int i = 0; i < 32; i += 8)
        out[(size_t)(bx + threadIdx.y + i) * HID + by + threadIdx.x] = tile[threadIdx.x][threadIdx.y + i];
}

__global__ void prep_kernel(const float* __restrict__ wq, const float* __restrict__ wk,
                            const float* __restrict__ bq, const float* __restrict__ bk) {
    int gw = (blockIdx.x * blockDim.x + threadIdx.x) >> 5;
    int lane = threadIdx.x & 31;
    if (gw > 2 * HID) return;
    const float* rowp;
    const float* vecp;
    if (gw < HID)            { rowp = wq + (size_t)gw * HID;          vecp = bk; }
    else if (gw < 2 * HID)   { rowp = wk + (size_t)(gw - HID) * HID;  vecp = bq; }
    else                     { rowp = bq;                             vecp = bk; }
    float acc = 0.f;
#pragma unroll
    for (int t = 0; t < HID / 32; t++)
        acc += rowp[lane + 32 * t] * vecp[lane + 32 * t];
    acc = warp_sum(acc);
    if (lane == 0) {
        if (gw < HID)          g_wcvec[gw] = acc;
        else if (gw < 2 * HID) g_rvec[gw - HID] = acc;
        else                   g_c0 = acc;
    }
}

__global__ void c_kernel(const float* __restrict__ smiles) {
    int gw = (blockIdx.x * blockDim.x + threadIdx.x) >> 5;
    int lane = threadIdx.x & 31;
    if (gw >= NB) return;
    const float* sp = smiles + (size_t)gw * HID;
    float acc = 0.f;
#pragma unroll
    for (int t = 0; t < HID / 32; t++)
        acc += sp[lane + 32 * t] * g_wcvec[lane + 32 * t];
    acc = warp_sum(acc);
    if (lane == 0) g_c[gw] = acc + g_c0;
}

// ---------------- tensor-core split-bf16 GEMM, fused fp32 load/convert ----------------
// (round-7 proven version; untouched)
#define ASTR 40
#define BSTR 72

template<bool BIAS, bool RELU, bool SPLITK>
__global__ __launch_bounds__(256)
void bgemm_kernel(const float* __restrict__ A, const float* __restrict__ B,
                  const float* __restrict__ bias, float* __restrict__ C,
                  int M, int N, int K, int lda)
{
    __shared__ __align__(16) __nv_bfloat16 sAh[128 * ASTR], sAl[128 * ASTR];
    __shared__ __align__(16) __nv_bfloat16 sBh[32 * BSTR],  sBl[32 * BSTR];

    const int tid  = threadIdx.x;
    const int lane = tid & 31, wid = tid >> 5;
    const int wm = wid >> 1, wn = wid & 1;
    const int row0 = blockIdx.y * 128, col0 = blockIdx.x * 64;
    const int koff = SPLITK ? blockIdx.z * K : 0;

    float acc[2][4][4];
#pragma unroll
    for (int mi = 0; mi < 2; mi++)
#pragma unroll
        for (int nj = 0; nj < 4; nj++)
#pragma unroll
            for (int q = 0; q < 4; q++) acc[mi][nj][q] = 0.f;

    int a_r[4], a_c[4], b_r[2], b_c[2];
    size_t a_off[4], b_off[2];
#pragma unroll
    for (int i = 0; i < 4; i++) {
        int idx = tid + i * 256;
        a_r[i] = idx >> 3; a_c[i] = (idx & 7) * 4;
        a_off[i] = (size_t)(row0 + a_r[i]) * lda + koff + a_c[i];
    }
#pragma unroll
    for (int i = 0; i < 2; i++) {
        int idx = tid + i * 256;
        b_r[i] = idx >> 4; b_c[i] = (idx & 15) * 4;
        b_off[i] = (size_t)(koff + b_r[i]) * N + col0 + b_c[i];
    }

    float4 pA[4], pB[2];
#pragma unroll
    for (int i = 0; i < 4; i++) pA[i] = *(const float4*)(A + a_off[i]);
#pragma unroll
    for (int i = 0; i < 2; i++) pB[i] = *(const float4*)(B + b_off[i]);

    const uint32_t sAh_u = s2u(sAh), sAl_u = s2u(sAl), sBh_u = s2u(sBh), sBl_u = s2u(sBl);
    const int a_lrow = wm * 32 + (lane & 15);
    const int a_lcol = ((lane >> 4) & 1) * 8;
    const int b_lrow = (lane & 7) + ((lane >> 3) & 1) * 8;
    const int b_lcol = wn * 32 + ((lane >> 4) & 1) * 8;

    const int NT = K / 32;
    for (int kt = 0; kt < NT; kt++) {
#pragma unroll
        for (int i = 0; i < 4; i++) {
            uint2 h, l; split4(pA[i], h, l);
            *(uint2*)&sAh[a_r[i] * ASTR + a_c[i]] = h;
            *(uint2*)&sAl[a_r[i] * ASTR + a_c[i]] = l;
        }
#pragma unroll
        for (int i = 0; i < 2; i++) {
            uint2 h, l; split4(pB[i], h, l);
            *(uint2*)&sBh[b_r[i] * BSTR + b_c[i]] = h;
            *(uint2*)&sBl[b_r[i] * BSTR + b_c[i]] = l;
        }
        __syncthreads();

        if (kt + 1 < NT) {
#pragma unroll
            for (int i = 0; i < 4; i++) pA[i] = *(const float4*)(A + a_off[i] + (size_t)(kt + 1) * 32);
#pragma unroll
            for (int i = 0; i < 2; i++) pB[i] = *(const float4*)(B + b_off[i] + (size_t)(kt + 1) * 32 * N);
        }

#pragma unroll
        for (int ks = 0; ks < 2; ks++) {
            uint32_t ah[2][4], al[2][4], bh[4][2], bl[4][2];
#pragma unroll
            for (int mi = 0; mi < 2; mi++) {
                uint32_t aoff = (uint32_t)(((a_lrow + mi * 16) * ASTR + ks * 16 + a_lcol) * 2);
                ldsm4(ah[mi][0], ah[mi][1], ah[mi][2], ah[mi][3], sAh_u + aoff);
                ldsm4(al[mi][0], al[mi][1], al[mi][2], al[mi][3], sAl_u + aoff);
            }
#pragma unroll
            for (int nj2 = 0; nj2 < 2; nj2++) {
                uint32_t boff = (uint32_t)(((ks * 16 + b_lrow) * BSTR + b_lcol + nj2 * 16) * 2);
                uint32_t t0, t1, t2, t3;
                ldsm4t(t0, t1, t2, t3, sBh_u + boff);
                bh[nj2 * 2][0] = t0; bh[nj2 * 2][1] = t1;
                bh[nj2 * 2 + 1][0] = t2; bh[nj2 * 2 + 1][1] = t3;
                ldsm4t(t0, t1, t2, t3, sBl_u + boff);
                bl[nj2 * 2][0] = t0; bl[nj2 * 2][1] = t1;
                bl[nj2 * 2 + 1][0] = t2; bl[nj2 * 2 + 1][1] = t3;
            }
#pragma unroll
            for (int mi = 0; mi < 2; mi++)
#pragma unroll
                for (int nj = 0; nj < 4; nj++) {
                    mma16816(acc[mi][nj], ah[mi], bh[nj]);
                    mma16816(acc[mi][nj], ah[mi], bl[nj]);
                    mma16816(acc[mi][nj], al[mi], bh[nj]);
                }
        }
        __syncthreads();
    }

    float* Cout = SPLITK ? C + (size_t)blockIdx.z * M * N : C;
#pragma unroll
    for (int mi = 0; mi < 2; mi++) {
        int r = row0 + wm * 32 + mi * 16 + (lane >> 2);
#pragma unroll
        for (int nj = 0; nj < 4; nj++) {
            int c = col0 + wn * 32 + nj * 8 + (lane & 3) * 2;
            float b0 = 0.f, b1 = 0.f;
            if (BIAS) { b0 = bias[c]; b1 = bias[c + 1]; }
            float v00 = acc[mi][nj][0] + b0, v01 = acc[mi][nj][1] + b1;
            float v10 = acc[mi][nj][2] + b0, v11 = acc[mi][nj][3] + b1;
            if (RELU) {
                v00 = fmaxf(v00, 0.f); v01 = fmaxf(v01, 0.f);
                v10 = fmaxf(v10, 0.f); v11 = fmaxf(v11, 0.f);
            }
            *(float2*)&Cout[(size_t)r * N + c]       = make_float2(v00, v01);
            *(float2*)&Cout[(size_t)(r + 8) * N + c] = make_float2(v10, v11);
        }
    }
}

// ---------------- fused score + softmax + weighted value sum ----------------
// block per graph: u[b] cached in smem (kills ~200MB of redundant L2 u-reads),
// scores cached in smem, denom, normalize, weighted value accumulation.
__global__ void score_attn_kernel(const float* __restrict__ key,
                                  const float* __restrict__ value,
                                  float* __restrict__ att_out) {
    __shared__ float u_s[HID];
    __shared__ float es[MAXSEG];
    int b = blockIdx.x, t = threadIdx.x;
    int lane = t & 31, w = t >> 5;
    int s0 = g_segstart[b], s1 = g_segstart[b + 1];
    int len = s1 - s0;
    u_s[t] = g_u[(size_t)b * HID + t];
    __syncthreads();
    float cb = g_c[b];

    // phase 1: per-node scores (warp per node, 8 nodes in flight)
    for (int i = s0 + w; i < s1; i += 8) {
        const float* kp = key + (size_t)i * HID;
        float acc = 0.f;
#pragma unroll
        for (int j = 0; j < 8; j++)
            acc += kp[lane + 32 * j] * u_s[lane + 32 * j];
        acc = warp_sum(acc);
        if (lane == 0) {
            float e = expf((acc + cb) * INV_SCALE);
            int idx = i - s0;
            if (idx < MAXSEG) es[idx] = e; else g_escore[i] = e;
        }
    }
    __syncthreads();

    // phase 2: denom
    float partial = 0.f;
    for (int idx = t; idx < len; idx += 256)
        partial += (idx < MAXSEG) ? es[idx] : g_escore[s0 + idx];
    float denom = block_sum_256(partial);

    // phase 3: attention output + weighted value sum
    float acc = 0.f;
    if (len > 0) {
        float invd = 1.f / denom;
        for (int idx = t; idx < len; idx += 256)
            att_out[s0 + idx] = ((idx < MAXSEG) ? es[idx] : g_escore[s0 + idx]) * invd;
#pragma unroll 4
        for (int idx = 0; idx < len; idx++) {
            float e = (idx < MAXSEG) ? es[idx] : g_escore[s0 + idx];
            acc += (e * invd) * value[(size_t)(s0 + idx) * HID + t];
        }
    }
    g_s[(size_t)b * HID + t] = acc;
}

__global__ void ln_kernel(const float* __restrict__ x, const float* __restrict__ r,
                          const float* __restrict__ g, const float* __restrict__ b,
                          float* __restrict__ out) {
    int row = blockIdx.x, t = threadIdx.x;
    float v = x[(size_t)row * HID + t] + r[(size_t)row * HID + t];
    float mu = block_sum_256(v) * (1.f / HID);
    float d = v - mu;
    float var = block_sum_256(d * d) * (1.f / HID);
    out[(size_t)row * HID + t] = d * rsqrtf(var + 1e-5f) * g[t] + b[t];
}

// reduce 4 split-K partials + bias, add residual, LN -> out
__global__ void ln2_reduce(const float* __restrict__ x1, const float* __restrict__ c2,
                           const float* __restrict__ g, const float* __restrict__ b,
                           float* __restrict__ out) {
    int row = blockIdx.x, t = threadIdx.x;
    size_t idx = (size_t)row * HID + t;
    const size_t STRIDE = (size_t)NB * HID;
    float h = g_hp[idx] + g_hp[idx + STRIDE] + g_hp[idx + 2 * STRIDE] + g_hp[idx + 3 * STRIDE] + c2[t];
    float v = x1[idx] + h;
    float mu = block_sum_256(v) * (1.f / HID);
    float d = v - mu;
    float var = block_sum_256(d * d) * (1.f / HID);
    out[idx] = d * rsqrtf(var + 1e-5f) * g[t] + b[t];
}

// ---------------- launcher ----------------
extern "C" void kernel_launch(void* const* d_in, const int* in_sizes, int n_in,
                              void* d_out, int out_size) {
    const float* smiles   = (const float*)d_in[0];
    const float* key_in   = (const float*)d_in[1];
    const float* value_in = (const float*)d_in[2];
    const int*   batch    = (const int*)  d_in[3];
    const float* wq   = (const float*)d_in[4];
    const float* bq   = (const float*)d_in[5];
    const float* wk   = (const float*)d_in[6];
    const float* bk   = (const float*)d_in[7];
    const float* wv   = (const float*)d_in[8];
    const float* bv   = (const float*)d_in[9];
    const float* ln0g = (const float*)d_in[10];
    const float* ln0b = (const float*)d_in[11];
    const float* ln1g = (const float*)d_in[12];
    const float* ln1b = (const float*)d_in[13];
    const float* w1   = (const float*)d_in[14];
    const float* c1   = (const float*)d_in[15];
    const float* w2   = (const float*)d_in[16];
    const float* c2   = (const float*)d_in[17];

    float* out        = (float*)d_out;
    float* out_smiles = out;
    float* out_att    = out + (size_t)NB * HID;

    float *U, *WkT, *M, *Rv, *S, *Dh, *X1, *H1, *Hp;
    cudaGetSymbolAddress((void**)&U,   g_u);
    cudaGetSymbolAddress((void**)&WkT, g_wkT);
    cudaGetSymbolAddress((void**)&M,   g_M);
    cudaGetSymbolAddress((void**)&Rv,  g_rvec);
    cudaGetSymbolAddress((void**)&S,   g_s);
    cudaGetSymbolAddress((void**)&Dh,  g_dh);
    cudaGetSymbolAddress((void**)&X1,  g_x1);
    cudaGetSymbolAddress((void**)&H1,  g_h1);
    cudaGetSymbolAddress((void**)&Hp,  g_hp);

    // order chosen so the 4th launch (ncu's profiled slot) is the big U-GEMM
    transpose_k<<<dim3(HID / 32, HID / 32), dim3(32, 8)>>>(wk, WkT);
    prep_kernel<<<(2 * HID + 1 + 7) / 8, 256>>>(wq, wk, bq, bk);
    // M = wq @ wk^T (small)
    bgemm_kernel<false, false, false><<<dim3(HID / 64, HID / 128), 256>>>(wq, WkT, nullptr, M, HID, HID, HID, HID);
    // U = smiles @ M + rvec   <-- profiled launch
    bgemm_kernel<true, false, false><<<dim3(HID / 64, NB / 128), 256>>>(smiles, M, Rv, U, NB, HID, HID, HID);

    seg_kernel<<<(NB + 1 + 255) / 256, 256>>>(batch);
    c_kernel<<<NB / 8, 256>>>(smiles);

    // fused per-graph score + softmax + weighted value sum
    score_attn_kernel<<<NB, 256>>>(key_in, value_in, out_att);

    // Dh = S @ wv + bv ; x1 = LN(smiles + Dh)
    bgemm_kernel<true, false, false><<<dim3(HID / 64, NB / 128), 256>>>(S, wv, bv, Dh, NB, HID, HID, HID);
    ln_kernel<<<NB, 256>>>(smiles, Dh, ln0g, ln0b, X1);

    // FFN1: H1 = relu(X1 @ w1 + c1)
    bgemm_kernel<true, true, false><<<dim3(HF4 / 64, NB / 128), 256>>>(X1, w1, c1, H1, NB, HF4, HID, HID);
    // FFN2 split-K=4: partials Hp[z] = H1 @ w2[z-slice]
    bgemm_kernel<false, false, true><<<dim3(HID / 64, NB / 128, 4), 256>>>(H1, w2, nullptr, Hp, NB, HID, HF4 / 4, HF4);
    // reduce partials + c2, add X1, LN -> out
    ln2_reduce<<<NB, 256>>>(X1, c2, ln1g, ln1b, out_smiles);
}